// round 6
// baseline (speedup 1.0000x reference)
#include <cuda_runtime.h>
#include <cuda_bf16.h>

#define BB 64
#define NN 256
#define DD 6
#define SS 4            // pair-kernel slices per batch -> 256 blocks total
#define EPSF 1e-8f
#define GOLDENF 1.618f

// Deterministic scratch (no atomics): per-batch partials and per-block pair partials.
__device__ float g_batch[BB][11];
__device__ float g_pair[BB * SS][3];

__device__ __forceinline__ float warpSum(float v) {
#pragma unroll
    for (int o = 16; o > 0; o >>= 1) v += __shfl_down_sync(0xffffffffu, v, o);
    return v;
}

// ---------------------------------------------------------------------------
// Kernel 1: per-element terms + per-batch reductions.
// grid = BB blocks, block = NN threads (one thread per element n of batch b).
// Quantities reduced per batch:
//  0: smoothL1(noise)  1: mse over dims 0..3   2: (1-iou)
//  3: mse layer(dim4)  4: mse conf(dim5)       5: |aspect-golden|
//  6: area sum         7: area^2 sum           8: cx sum
//  9: cy sum          10: mask sum (valid count)
// ---------------------------------------------------------------------------
__global__ void k_elem(const float* __restrict__ pnoise, const float* __restrict__ tnoise,
                       const float* __restrict__ play,   const float* __restrict__ tlay,
                       const float* __restrict__ mask)
{
    int b = blockIdx.x;
    int n = threadIdx.x;
    int idx = b * NN + n;
    float m = mask[idx];
    const float* pp  = play   + idx * DD;
    const float* tt  = tlay   + idx * DD;
    const float* pnp = pnoise + idx * DD;
    const float* tnp = tnoise + idx * DD;

    // noise smooth-L1 over 6 dims (masked values)
    float nl = 0.f;
#pragma unroll
    for (int d = 0; d < 6; d++) {
        float a = fabsf(pnp[d] * m - tnp[d] * m);
        nl += (a < 1.f) ? 0.5f * a * a : a - 0.5f;
    }

    float pl0 = pp[0] * m, pl1 = pp[1] * m, pl2 = pp[2] * m;
    float pl3 = pp[3] * m, pl4 = pp[4] * m, pl5 = pp[5] * m;
    float tl0 = tt[0] * m, tl1 = tt[1] * m, tl2 = tt[2] * m;
    float tl3 = tt[3] * m, tl4 = tt[4] * m, tl5 = tt[5] * m;

    float d0 = pl0 - tl0, d1 = pl1 - tl1, d2 = pl2 - tl2, d3 = pl3 - tl3;
    float mse4 = d0 * d0 + d1 * d1 + d2 * d2 + d3 * d3;

    // IoU(pred, target) boxes (x,y,w,h)
    float px2 = pl0 + pl2, py2 = pl1 + pl3;
    float tx2 = tl0 + tl2, ty2 = tl1 + tl3;
    float iw = fmaxf(fminf(px2, tx2) - fmaxf(pl0, tl0), 0.f);
    float ih = fmaxf(fminf(py2, ty2) - fmaxf(pl1, tl1), 0.f);
    float inter = iw * ih;
    float pa = pl2 * pl3, ta = tl2 * tl3;
    float iou = inter / (pa + ta - inter + EPSF);
    float iouL = 1.f - iou;

    float lmse = (pl4 - tl4) * (pl4 - tl4);
    float cmse = (pl5 - tl5) * (pl5 - tl5);

    float aspect = pl2 / (pl3 + EPSF);
    float gold = fabsf(aspect - GOLDENF);

    float area = pl2 * pl3 * m;
    float area2 = area * area;
    float cx = (pl0 + 0.5f * pl2) * m;
    float cy = (pl1 + 0.5f * pl3) * m;

    float v[11] = {nl, mse4, iouL, lmse, cmse, gold, area, area2, cx, cy, m};

    __shared__ float sh[8][11];
    int wid = n >> 5, lane = n & 31;
#pragma unroll
    for (int q = 0; q < 11; q++) {
        float s = warpSum(v[q]);
        if (lane == 0) sh[wid][q] = s;
    }
    __syncthreads();
    if (n < 11) {
        float s = 0.f;
#pragma unroll
        for (int r = 0; r < 8; r++) s += sh[r][n];
        g_batch[b][n] = s;
    }
}

// ---------------------------------------------------------------------------
// Kernel 2: pairwise terms (ranking BCE, overlap, alignment).
// grid = (BB, SS), block = 256 threads. Worker w = blockIdx.y*256 + tid owns
// balanced row-pair (rp, 255-rp) with inner j-loop strided 2*SS = 8 ways.
// ---------------------------------------------------------------------------
__global__ void k_pair(const float* __restrict__ play, const float* __restrict__ tlay,
                       const float* __restrict__ mask)
{
    __shared__ float splr[NN], stlr[NN], sx1[NN], sx2[NN], sy1[NN], sy2[NN],
                     sex[NN], sey[NN], sar[NN], smk[NN];
    int b = blockIdx.x;
    int t = threadIdx.x;

    {
        int idx = b * NN + t;
        float m = mask[idx];
        const float* pp = play + idx * DD;
        const float* tt = tlay + idx * DD;
        float x = pp[0] * m, y = pp[1] * m, w = pp[2] * m, h = pp[3] * m;
        splr[t] = pp[4] * m;
        stlr[t] = tt[4] * m;
        sx1[t] = x; sx2[t] = x + w;
        sy1[t] = y; sy2[t] = y + h;
        sex[t] = x + 0.5f * w;
        sey[t] = y + 0.5f * h;
        sar[t] = w * h;
        smk[t] = m;
    }
    __syncthreads();

    int wkr = blockIdx.y * 256 + t;      // [0, SS*256)
    int rp  = wkr & 127;                 // row-pair id
    int sub = wkr >> 7;                  // [0, 2*SS)
    const int stride = 2 * SS;

    float rank = 0.f, ov = 0.f, al = 0.f;
    int rows[2] = {rp, NN - 1 - rp};
#pragma unroll
    for (int r = 0; r < 2; r++) {
        int i = rows[r];
        float pi = splr[i], ti = stlr[i];
        float xi1 = sx1[i], xi2 = sx2[i], yi1 = sy1[i], yi2 = sy2[i];
        float exi = sex[i], eyi = sey[i], ai = sar[i], mi = smk[i];
        for (int j = i + 1 + sub; j < NN; j += stride) {
            // ranking BCE: diff[b,i,j] = p_j - p_i ; y = (t_i < t_j)
            float d = splr[j] - pi;
            float ad = fabsf(d);
            float sp = log1pf(__expf(-ad));          // softplus(-|d|)
            float bce = (ti < stlr[j]) ? fminf(sp + fmaxf(-d, 0.f), 100.f)
                                       : fminf(sp + fmaxf(d, 0.f), 100.f);
            rank += bce;

            float pm = mi * smk[j];

            // overlap ratio
            float iw = fmaxf(fminf(xi2, sx2[j]) - fmaxf(xi1, sx1[j]), 0.f);
            float ih = fmaxf(fminf(yi2, sy2[j]) - fmaxf(yi1, sy1[j]), 0.f);
            ov += (iw * ih) / (fminf(ai, sar[j]) + EPSF) * pm;

            // alignment: 6 edges, penalty dist/5 if dist < 5
            float a6 = 0.f, dd;
            dd = fabsf(xi1 - sx1[j]); a6 += (dd < 5.f) ? dd : 0.f;
            dd = fabsf(xi2 - sx2[j]); a6 += (dd < 5.f) ? dd : 0.f;
            dd = fabsf(yi1 - sy1[j]); a6 += (dd < 5.f) ? dd : 0.f;
            dd = fabsf(yi2 - sy2[j]); a6 += (dd < 5.f) ? dd : 0.f;
            dd = fabsf(exi - sex[j]); a6 += (dd < 5.f) ? dd : 0.f;
            dd = fabsf(eyi - sey[j]); a6 += (dd < 5.f) ? dd : 0.f;
            al += a6 * pm;
        }
    }
    al *= 0.2f;  // /ALIGN_THRESH (linear, hoisted)

    __shared__ float sh[8][3];
    int wid = t >> 5, lane = t & 31;
    float vv[3] = {rank, ov, al};
#pragma unroll
    for (int q = 0; q < 3; q++) {
        float s = warpSum(vv[q]);
        if (lane == 0) sh[wid][q] = s;
    }
    __syncthreads();
    if (t < 3) {
        float s = 0.f;
#pragma unroll
        for (int r = 0; r < 8; r++) s += sh[r][t];
        g_pair[b * SS + blockIdx.y][t] = s;
    }
}

// ---------------------------------------------------------------------------
// Kernel 3: combine everything into the scalar loss. 1 block, 256 threads.
// ---------------------------------------------------------------------------
__device__ __forceinline__ float blockSum256(float v, float* red) {
    int t = threadIdx.x;
    red[t] = v;
    __syncthreads();
#pragma unroll
    for (int s = 128; s > 0; s >>= 1) {
        if (t < s) red[t] += red[t + s];
        __syncthreads();
    }
    float r = red[0];
    __syncthreads();
    return r;
}

__global__ void k_final(float* __restrict__ out)
{
    __shared__ float scx[BB], scy[BB], svc[BB];
    __shared__ float red[256];
    int t = threadIdx.x;

    float nl = 0.f, mse4 = 0.f, iou = 0.f, lm = 0.f, cm = 0.f, gd = 0.f;
    float ar = 0.f, stdv = 0.f;
    if (t < BB) {
        const float* gb = g_batch[t];
        nl = gb[0]; mse4 = gb[1]; iou = gb[2]; lm = gb[3]; cm = gb[4]; gd = gb[5];
        float sa = gb[6], sa2 = gb[7];
        ar = sa;
        float var = (sa2 - sa * sa / (float)NN) / (float)(NN - 1);   // ddof=1
        stdv = sqrtf(fmaxf(var, 0.f));
        scx[t] = gb[8]; scy[t] = gb[9]; svc[t] = gb[10];
    }
    // pairwise partials: 256 rows, one per thread
    float rank = g_pair[t][0];
    float ov   = g_pair[t][1];
    float al   = g_pair[t][2];
    __syncthreads();

    // balance: faithful [B]/[B,1] broadcast -> B x B terms
    float bal = 0.f;
    for (int k = t; k < BB * BB; k += 256) {
        int i = k >> 6;          // row of valid_count
        int j = k & 63;          // column of center sums
        float inv = 1.f / (svc[i] + EPSF);
        float ocx = scx[j] * inv;
        float ocy = scy[j] * inv;
        bal += fabsf(ocx - 512.f) * (1.f / 512.f) + fabsf(ocy - 512.f) * (1.f / 512.f);
    }

    float NL   = blockSum256(nl,   red);
    float MSE4 = blockSum256(mse4, red);
    float IOU  = blockSum256(iou,  red);
    float LM   = blockSum256(lm,   red);
    float CM   = blockSum256(cm,   red);
    float GD   = blockSum256(gd,   red);
    float AR   = blockSum256(ar,   red);
    float STDS = blockSum256(stdv, red);
    float RANK = blockSum256(rank, red);
    float OV   = blockSum256(ov,   red);
    float AL   = blockSum256(al,   red);
    float BAL  = blockSum256(bal,  red);

    if (t == 0) {
        const float BN = (float)(BB * NN);                 // 16384
        const float npairs = (float)NN * (NN - 1) * 0.5f;  // 32640

        float noise_loss = NL / (BN * 6.f);
        float position_loss = MSE4 / (BN * 4.f) + 0.5f * (IOU / BN);
        float ranking = RANK / ((float)BB * npairs);
        float layer_loss = LM / BN + 0.3f * ranking;
        float conf_loss = CM / BN;
        float golden = GD / BN;
        float mean_area = AR / BN;
        float size_harm = (STDS / (float)BB) / (mean_area + EPSF);
        float balance = BAL / (float)(BB * BB);
        float aesthetic = 0.1f * golden + 0.2f * size_harm + 0.15f * balance;
        float overlap = OV / ((float)BB * npairs);
        float align = AL / ((float)BB * 6.f * npairs);

        out[0] = noise_loss + 1.0f * position_loss + 0.5f * layer_loss +
                 0.3f * conf_loss + 0.2f * aesthetic + 0.8f * overlap +
                 0.4f * align;
    }
}

extern "C" void kernel_launch(void* const* d_in, const int* in_sizes, int n_in,
                              void* d_out, int out_size)
{
    const float* pnoise = (const float*)d_in[0];
    const float* tnoise = (const float*)d_in[1];
    const float* play   = (const float*)d_in[2];
    const float* tlay   = (const float*)d_in[3];
    const float* mask   = (const float*)d_in[4];
    float* out = (float*)d_out;

    k_elem<<<BB, NN>>>(pnoise, tnoise, play, tlay, mask);
    dim3 g2(BB, SS);
    k_pair<<<g2, 256>>>(play, tlay, mask);
    k_final<<<1, 256>>>(out);
}

// round 8
// speedup vs baseline: 2.6972x; 2.6972x over previous
#include <cuda_runtime.h>
#include <cuda_bf16.h>

#define BB 64
#define NN 256
#define DD 6
#define SS 8            // pair-kernel slices per batch -> 512 blocks total
#define EPSF 1e-8f
#define GOLDENF 1.618f

// Deterministic scratch (no atomics).
__device__ float g_batch[BB][11];
__device__ float g_pair[BB * SS][3];

__device__ __forceinline__ float warpSum(float v) {
#pragma unroll
    for (int o = 16; o > 0; o >>= 1) v += __shfl_down_sync(0xffffffffu, v, o);
    return v;
}

// ---------------------------------------------------------------------------
// Fused kernel: pairwise terms in every block; y==0 blocks also do the
// per-element terms + per-batch reduction (data is already hot).
// grid = (BB, SS), block = 256 threads.
// ---------------------------------------------------------------------------
__global__ void __launch_bounds__(256) k_main(
    const float* __restrict__ pnoise, const float* __restrict__ tnoise,
    const float* __restrict__ play,   const float* __restrict__ tlay,
    const float* __restrict__ mask)
{
    __shared__ float4 sbox[NN];   // x1, y1, x2, y2
    __shared__ float4 smsc[NN];   // ex, ey, area, mask
    __shared__ float2 slyr[NN];   // p_layer, t_layer
    __shared__ float  sh[8][11];

    int b = blockIdx.x;
    int t = threadIdx.x;
    int idx = b * NN + t;
    float m = mask[idx];
    const float* pp = play + idx * DD;
    const float* tt = tlay + idx * DD;

    float pl0 = pp[0] * m, pl1 = pp[1] * m, pl2 = pp[2] * m;
    float pl3 = pp[3] * m, pl4 = pp[4] * m, pl5 = pp[5] * m;
    float tl4 = tt[4] * m;

    sbox[t] = make_float4(pl0, pl1, pl0 + pl2, pl1 + pl3);
    smsc[t] = make_float4(pl0 + 0.5f * pl2, pl1 + 0.5f * pl3, pl2 * pl3, m);
    slyr[t] = make_float2(pl4, tl4);

    if (blockIdx.y == 0) {
        // ---- element terms (one element per thread) ----
        const float* pnp = pnoise + idx * DD;
        const float* tnp = tnoise + idx * DD;
        float nl = 0.f;
#pragma unroll
        for (int d = 0; d < 6; d++) {
            float a = fabsf(pnp[d] * m - tnp[d] * m);
            nl += (a < 1.f) ? 0.5f * a * a : a - 0.5f;
        }
        float tl0 = tt[0] * m, tl1 = tt[1] * m, tl2 = tt[2] * m;
        float tl3 = tt[3] * m, tl5 = tt[5] * m;

        float d0 = pl0 - tl0, d1 = pl1 - tl1, d2 = pl2 - tl2, d3 = pl3 - tl3;
        float mse4 = d0 * d0 + d1 * d1 + d2 * d2 + d3 * d3;

        float iw = fmaxf(fminf(pl0 + pl2, tl0 + tl2) - fmaxf(pl0, tl0), 0.f);
        float ih = fmaxf(fminf(pl1 + pl3, tl1 + tl3) - fmaxf(pl1, tl1), 0.f);
        float inter = iw * ih;
        float pa = pl2 * pl3, ta = tl2 * tl3;
        float iouL = 1.f - inter / (pa + ta - inter + EPSF);

        float lmse = (pl4 - tl4) * (pl4 - tl4);
        float cmse = (pl5 - tl5) * (pl5 - tl5);
        float gold = fabsf(pl2 / (pl3 + EPSF) - GOLDENF);

        float area = pl2 * pl3 * m;
        float cx = (pl0 + 0.5f * pl2) * m;
        float cy = (pl1 + 0.5f * pl3) * m;

        float v[11] = {nl, mse4, iouL, lmse, cmse, gold,
                       area, area * area, cx, cy, m};
        int wid = t >> 5, lane = t & 31;
#pragma unroll
        for (int q = 0; q < 11; q++) {
            float s = warpSum(v[q]);
            if (lane == 0) sh[wid][q] = s;
        }
        __syncthreads();
        if (t < 11) {
            float s = 0.f;
#pragma unroll
            for (int r = 0; r < 8; r++) s += sh[r][t];
            g_batch[b][t] = s;
        }
        __syncthreads();   // sh reused below
    } else {
        __syncthreads();   // publish shared tiles
    }

    // ---- pairwise terms ----
    int wkr = blockIdx.y * 256 + t;      // [0, SS*256)
    int rp  = wkr & 127;                 // balanced row-pair id
    int sub = wkr >> 7;                  // [0, 2*SS)
    const int stride = 2 * SS;

    float rank = 0.f, ov = 0.f, al = 0.f;
    int rows[2] = {rp, NN - 1 - rp};
#pragma unroll
    for (int r = 0; r < 2; r++) {
        int i = rows[r];
        float2 li = slyr[i];
        float4 bi = sbox[i];
        float4 ci = smsc[i];
#pragma unroll 4
        for (int j = i + 1 + sub; j < NN; j += stride) {
            float2 lj = slyr[j];
            float4 bj = sbox[j];
            float4 cj = smsc[j];

            // ranking BCE: d = p_j - p_i ; y = (t_i < t_j)
            float d = lj.x - li.x;
            float ad = fabsf(d);
            float base = __logf(1.f + __expf(-ad));      // softplus(-|d|)
            float sg = (li.y < lj.y) ? -d : d;
            rank += fminf(base + fmaxf(sg, 0.f), 100.f);

            float pm = ci.w * cj.w;

            // overlap ratio
            float iw = fmaxf(fminf(bi.z, bj.z) - fmaxf(bi.x, bj.x), 0.f);
            float ih = fmaxf(fminf(bi.w, bj.w) - fmaxf(bi.y, bj.y), 0.f);
            ov += __fdividef(iw * ih, fminf(ci.z, cj.z) + EPSF) * pm;

            // alignment: 6 edges, penalty dist/5 if dist < 5 (the /5 hoisted)
            float a6 = 0.f, dd;
            dd = fabsf(bi.x - bj.x); a6 += (dd < 5.f) ? dd : 0.f;
            dd = fabsf(bi.z - bj.z); a6 += (dd < 5.f) ? dd : 0.f;
            dd = fabsf(bi.y - bj.y); a6 += (dd < 5.f) ? dd : 0.f;
            dd = fabsf(bi.w - bj.w); a6 += (dd < 5.f) ? dd : 0.f;
            dd = fabsf(ci.x - cj.x); a6 += (dd < 5.f) ? dd : 0.f;
            dd = fabsf(ci.y - cj.y); a6 += (dd < 5.f) ? dd : 0.f;
            al += a6 * pm;
        }
    }
    al *= 0.2f;

    int wid = t >> 5, lane = t & 31;
    float vv[3] = {rank, ov, al};
#pragma unroll
    for (int q = 0; q < 3; q++) {
        float s = warpSum(vv[q]);
        if (lane == 0) sh[wid][q] = s;
    }
    __syncthreads();
    if (t < 3) {
        float s = 0.f;
#pragma unroll
        for (int r = 0; r < 8; r++) s += sh[r][t];
        g_pair[b * SS + blockIdx.y][t] = s;
    }
}

// ---------------------------------------------------------------------------
// Final combine: 1 block, 256 threads, single fused reduction.
// ---------------------------------------------------------------------------
__global__ void __launch_bounds__(256) k_final(float* __restrict__ out)
{
    __shared__ float scx[BB], scy[BB], svc[BB];
    __shared__ float sh[8][12];
    __shared__ float tot[12];
    int t = threadIdx.x;

    float v[12];
#pragma unroll
    for (int q = 0; q < 12; q++) v[q] = 0.f;

    if (t < BB) {
        const float* gb = g_batch[t];
        v[0] = gb[0];   // noise smoothL1 sum
        v[1] = gb[1];   // mse4
        v[2] = gb[2];   // 1-iou
        v[3] = gb[3];   // layer mse
        v[4] = gb[4];   // conf mse
        v[5] = gb[5];   // golden
        v[6] = gb[6];   // area sum
        float sa = gb[6], sa2 = gb[7];
        float var = (sa2 - sa * sa * (1.f / (float)NN)) * (1.f / (float)(NN - 1));
        v[7] = sqrtf(fmaxf(var, 0.f));   // per-batch std (ddof=1)
        scx[t] = gb[8]; scy[t] = gb[9]; svc[t] = gb[10];
    }
    // pair partials: 512 rows, 2 per thread
    v[8]  = g_pair[t][0] + g_pair[t + 256][0];
    v[9]  = g_pair[t][1] + g_pair[t + 256][1];
    v[10] = g_pair[t][2] + g_pair[t + 256][2];
    __syncthreads();

    // balance: faithful [B]/[B,1] broadcast -> B x B terms
    float bal = 0.f;
#pragma unroll
    for (int k = t; k < BB * BB; k += 256) {
        int i = k >> 6;          // row: valid_count index
        int j = k & 63;          // col: center-sum index
        float inv = 1.f / (svc[i] + EPSF);
        bal += (fabsf(scx[j] * inv - 512.f) + fabsf(scy[j] * inv - 512.f)) * (1.f / 512.f);
    }
    v[11] = bal;

    int wid = t >> 5, lane = t & 31;
#pragma unroll
    for (int q = 0; q < 12; q++) {
        float s = warpSum(v[q]);
        if (lane == 0) sh[wid][q] = s;
    }
    __syncthreads();
    if (t < 12) {
        float s = 0.f;
#pragma unroll
        for (int r = 0; r < 8; r++) s += sh[r][t];
        tot[t] = s;
    }
    __syncthreads();

    if (t == 0) {
        const float BN = (float)(BB * NN);                 // 16384
        const float npairs = (float)NN * (NN - 1) * 0.5f;  // 32640

        float noise_loss = tot[0] / (BN * 6.f);
        float position_loss = tot[1] / (BN * 4.f) + 0.5f * (tot[2] / BN);
        float ranking = tot[8] / ((float)BB * npairs);
        float layer_loss = tot[3] / BN + 0.3f * ranking;
        float conf_loss = tot[4] / BN;
        float golden = tot[5] / BN;
        float mean_area = tot[6] / BN;
        float size_harm = (tot[7] / (float)BB) / (mean_area + EPSF);
        float balance = tot[11] / (float)(BB * BB);
        float aesthetic = 0.1f * golden + 0.2f * size_harm + 0.15f * balance;
        float overlap = tot[9] / ((float)BB * npairs);
        float align = tot[10] / ((float)BB * 6.f * npairs);

        out[0] = noise_loss + 1.0f * position_loss + 0.5f * layer_loss +
                 0.3f * conf_loss + 0.2f * aesthetic + 0.8f * overlap +
                 0.4f * align;
    }
}

extern "C" void kernel_launch(void* const* d_in, const int* in_sizes, int n_in,
                              void* d_out, int out_size)
{
    const float* pnoise = (const float*)d_in[0];
    const float* tnoise = (const float*)d_in[1];
    const float* play   = (const float*)d_in[2];
    const float* tlay   = (const float*)d_in[3];
    const float* mask   = (const float*)d_in[4];
    float* out = (float*)d_out;

    dim3 g(BB, SS);
    k_main<<<g, 256>>>(pnoise, tnoise, play, tlay, mask);
    k_final<<<1, 256>>>(out);
}

// round 9
// speedup vs baseline: 2.7330x; 1.0133x over previous
#include <cuda_runtime.h>
#include <cuda_bf16.h>

#define BB 64
#define NN 256
#define DD 6
#define SS 8                       // slices per batch -> 512 blocks total
#define NBLK (BB * SS)
#define EPSF 1e-8f
#define GOLDENF 1.618f

// Deterministic scratch (no FP atomics; counter only signals readiness).
__device__ float g_batch[BB][11];
__device__ float g_pair[NBLK][3];
__device__ int   g_count = 0;

__device__ __forceinline__ float warpSum(float v) {
#pragma unroll
    for (int o = 16; o > 0; o >>= 1) v += __shfl_down_sync(0xffffffffu, v, o);
    return v;
}

// ---------------------------------------------------------------------------
// Single fused kernel. grid = (BB, SS), block = 256.
//  - all blocks: pairwise terms (ranking BCE / overlap / alignment)
//  - y==0 blocks: per-element terms + per-batch reduction
//  - last block to finish: global combine -> out[0]
// ---------------------------------------------------------------------------
__global__ void __launch_bounds__(256) k_all(
    const float* __restrict__ pnoise, const float* __restrict__ tnoise,
    const float* __restrict__ play,   const float* __restrict__ tlay,
    const float* __restrict__ mask,   float* __restrict__ out)
{
    __shared__ float  raw_p[NN * DD];   // 6 KB staging (reused for noise)
    __shared__ float  raw_t[NN * DD];
    __shared__ float4 sbox[NN];         // x1, y1, x2, y2
    __shared__ float4 smsc[NN];         // ex, ey, area, mask
    __shared__ float2 slyr[NN];         // p_layer, t_layer
    __shared__ float  sh[8][12];
    __shared__ float  scx[BB], scy[BB], svc[BB], tot[12];
    __shared__ int    last;

    int b = blockIdx.x;
    int t = threadIdx.x;
    int wid = t >> 5, lane = t & 31;

    // ---- coalesced staging of the batch slice (1536 floats each) ----
    {
        const float4* p4 = (const float4*)(play + b * (NN * DD));
        const float4* t4 = (const float4*)(tlay + b * (NN * DD));
        float4* rp = (float4*)raw_p;
        float4* rt = (float4*)raw_t;
        rp[t] = p4[t];
        rt[t] = t4[t];
        if (t < 128) { rp[256 + t] = p4[256 + t]; rt[256 + t] = t4[256 + t]; }
    }
    float m = mask[b * NN + t];
    __syncthreads();

    float pl0 = raw_p[t * 6 + 0] * m, pl1 = raw_p[t * 6 + 1] * m;
    float pl2 = raw_p[t * 6 + 2] * m, pl3 = raw_p[t * 6 + 3] * m;
    float pl4 = raw_p[t * 6 + 4] * m, pl5 = raw_p[t * 6 + 5] * m;
    float tl4 = raw_t[t * 6 + 4] * m;

    sbox[t] = make_float4(pl0, pl1, pl0 + pl2, pl1 + pl3);
    smsc[t] = make_float4(pl0 + 0.5f * pl2, pl1 + 0.5f * pl3, pl2 * pl3, m);
    slyr[t] = make_float2(pl4, tl4);

    if (blockIdx.y == 0) {
        // ---- element terms (uses raw_t for target row, then reuses raws for noise) ----
        float tl0 = raw_t[t * 6 + 0] * m, tl1 = raw_t[t * 6 + 1] * m;
        float tl2 = raw_t[t * 6 + 2] * m, tl3 = raw_t[t * 6 + 3] * m;
        float tl5 = raw_t[t * 6 + 5] * m;

        float d0 = pl0 - tl0, d1 = pl1 - tl1, d2 = pl2 - tl2, d3 = pl3 - tl3;
        float mse4 = d0 * d0 + d1 * d1 + d2 * d2 + d3 * d3;

        float iw = fmaxf(fminf(pl0 + pl2, tl0 + tl2) - fmaxf(pl0, tl0), 0.f);
        float ih = fmaxf(fminf(pl1 + pl3, tl1 + tl3) - fmaxf(pl1, tl1), 0.f);
        float inter = iw * ih;
        float pa = pl2 * pl3, ta = tl2 * tl3;
        float iouL = 1.f - inter / (pa + ta - inter + EPSF);

        float lmse = (pl4 - tl4) * (pl4 - tl4);
        float cmse = (pl5 - tl5) * (pl5 - tl5);
        float gold = fabsf(pl2 / (pl3 + EPSF) - GOLDENF);
        float area = pl2 * pl3 * m;
        float cx = (pl0 + 0.5f * pl2) * m;
        float cy = (pl1 + 0.5f * pl3) * m;

        // coalesced noise staging into the (now free) raw buffers
        __syncthreads();
        {
            const float4* p4 = (const float4*)(pnoise + b * (NN * DD));
            const float4* t4 = (const float4*)(tnoise + b * (NN * DD));
            float4* rp = (float4*)raw_p;
            float4* rt = (float4*)raw_t;
            rp[t] = p4[t];
            rt[t] = t4[t];
            if (t < 128) { rp[256 + t] = p4[256 + t]; rt[256 + t] = t4[256 + t]; }
        }
        __syncthreads();
        float nl = 0.f;
#pragma unroll
        for (int d = 0; d < 6; d++) {
            float a = fabsf(raw_p[t * 6 + d] * m - raw_t[t * 6 + d] * m);
            nl += (a < 1.f) ? 0.5f * a * a : a - 0.5f;
        }

        float v[11] = {nl, mse4, iouL, lmse, cmse, gold,
                       area, area * area, cx, cy, m};
#pragma unroll
        for (int q = 0; q < 11; q++) {
            float s = warpSum(v[q]);
            if (lane == 0) sh[wid][q] = s;
        }
        __syncthreads();
        if (t < 11) {
            float s = 0.f;
#pragma unroll
            for (int r = 0; r < 8; r++) s += sh[r][t];
            g_batch[b][t] = s;
            __threadfence();          // publish before the counter bump
        }
        __syncthreads();              // sh reused below
    } else {
        __syncthreads();              // publish derived tiles
    }

    // ---- pairwise terms ----
    int wkr = blockIdx.y * 256 + t;
    int rp  = wkr & 127;              // balanced row-pair
    int sub = wkr >> 7;               // [0, 2*SS)
    const int stride = 2 * SS;

    float rank = 0.f, ov = 0.f, al = 0.f;
    int rows[2] = {rp, NN - 1 - rp};
#pragma unroll
    for (int r = 0; r < 2; r++) {
        int i = rows[r];
        float2 li = slyr[i];
        float4 bi = sbox[i];
        float4 ci = smsc[i];
#pragma unroll 4
        for (int j = i + 1 + sub; j < NN; j += stride) {
            float2 lj = slyr[j];
            float4 bj = sbox[j];
            float4 cj = smsc[j];

            float d = lj.x - li.x;
            float ad = fabsf(d);
            float base = __logf(1.f + __expf(-ad));      // softplus(-|d|)
            float sg = (li.y < lj.y) ? -d : d;
            rank += fminf(base + fmaxf(sg, 0.f), 100.f);

            float pm = ci.w * cj.w;

            float iw = fmaxf(fminf(bi.z, bj.z) - fmaxf(bi.x, bj.x), 0.f);
            float ih = fmaxf(fminf(bi.w, bj.w) - fmaxf(bi.y, bj.y), 0.f);
            ov += __fdividef(iw * ih, fminf(ci.z, cj.z) + EPSF) * pm;

            float a6 = 0.f, dd;
            dd = fabsf(bi.x - bj.x); a6 += (dd < 5.f) ? dd : 0.f;
            dd = fabsf(bi.z - bj.z); a6 += (dd < 5.f) ? dd : 0.f;
            dd = fabsf(bi.y - bj.y); a6 += (dd < 5.f) ? dd : 0.f;
            dd = fabsf(bi.w - bj.w); a6 += (dd < 5.f) ? dd : 0.f;
            dd = fabsf(ci.x - cj.x); a6 += (dd < 5.f) ? dd : 0.f;
            dd = fabsf(ci.y - cj.y); a6 += (dd < 5.f) ? dd : 0.f;
            al += a6 * pm;
        }
    }
    al *= 0.2f;   // /ALIGN_THRESH hoisted

    float vv[3] = {rank, ov, al};
#pragma unroll
    for (int q = 0; q < 3; q++) {
        float s = warpSum(vv[q]);
        if (lane == 0) sh[wid][q] = s;
    }
    __syncthreads();
    if (t < 3) {
        float s = 0.f;
#pragma unroll
        for (int r = 0; r < 8; r++) s += sh[r][t];
        g_pair[b * SS + blockIdx.y][t] = s;
        __threadfence();              // publish before the counter bump
    }
    __syncthreads();

    // ---- last-block finalization ----
    if (t == 0) last = (atomicAdd(&g_count, 1) == NBLK - 1);
    __syncthreads();
    if (!last) return;

    __threadfence();                  // acquire: see all published partials

    float v[12];
#pragma unroll
    for (int q = 0; q < 12; q++) v[q] = 0.f;

    if (t < BB) {
        const float* gb = g_batch[t];
        v[0] = gb[0]; v[1] = gb[1]; v[2] = gb[2];
        v[3] = gb[3]; v[4] = gb[4]; v[5] = gb[5];
        v[6] = gb[6];
        float sa = gb[6], sa2 = gb[7];
        float var = (sa2 - sa * sa * (1.f / (float)NN)) * (1.f / (float)(NN - 1));
        v[7] = sqrtf(fmaxf(var, 0.f));     // per-batch std, ddof=1
        scx[t] = gb[8]; scy[t] = gb[9]; svc[t] = gb[10];
    }
    v[8]  = g_pair[t][0] + g_pair[t + 256][0];
    v[9]  = g_pair[t][1] + g_pair[t + 256][1];
    v[10] = g_pair[t][2] + g_pair[t + 256][2];
    __syncthreads();

    // balance: faithful [B]/[B,1] broadcast -> B x B terms
    float bal = 0.f;
#pragma unroll
    for (int k = t; k < BB * BB; k += 256) {
        int i = k >> 6;
        int j = k & 63;
        float inv = 1.f / (svc[i] + EPSF);
        bal += (fabsf(scx[j] * inv - 512.f) + fabsf(scy[j] * inv - 512.f)) * (1.f / 512.f);
    }
    v[11] = bal;

#pragma unroll
    for (int q = 0; q < 12; q++) {
        float s = warpSum(v[q]);
        if (lane == 0) sh[wid][q] = s;
    }
    __syncthreads();
    if (t < 12) {
        float s = 0.f;
#pragma unroll
        for (int r = 0; r < 8; r++) s += sh[r][t];
        tot[t] = s;
    }
    __syncthreads();

    if (t == 0) {
        const float BN = (float)(BB * NN);                 // 16384
        const float npairs = (float)NN * (NN - 1) * 0.5f;  // 32640

        float noise_loss = tot[0] / (BN * 6.f);
        float position_loss = tot[1] / (BN * 4.f) + 0.5f * (tot[2] / BN);
        float ranking = tot[8] / ((float)BB * npairs);
        float layer_loss = tot[3] / BN + 0.3f * ranking;
        float conf_loss = tot[4] / BN;
        float golden = tot[5] / BN;
        float mean_area = tot[6] / BN;
        float size_harm = (tot[7] / (float)BB) / (mean_area + EPSF);
        float balance = tot[11] / (float)(BB * BB);
        float aesthetic = 0.1f * golden + 0.2f * size_harm + 0.15f * balance;
        float overlap = tot[9] / ((float)BB * npairs);
        float align = tot[10] / ((float)BB * 6.f * npairs);

        out[0] = noise_loss + 1.0f * position_loss + 0.5f * layer_loss +
                 0.3f * conf_loss + 0.2f * aesthetic + 0.8f * overlap +
                 0.4f * align;

        g_count = 0;                   // reset for next graph replay
    }
}

extern "C" void kernel_launch(void* const* d_in, const int* in_sizes, int n_in,
                              void* d_out, int out_size)
{
    const float* pnoise = (const float*)d_in[0];
    const float* tnoise = (const float*)d_in[1];
    const float* play   = (const float*)d_in[2];
    const float* tlay   = (const float*)d_in[3];
    const float* mask   = (const float*)d_in[4];
    float* out = (float*)d_out;

    dim3 g(BB, SS);
    k_all<<<g, 256>>>(pnoise, tnoise, play, tlay, mask, out);
}